// round 15
// baseline (speedup 1.0000x reference)
#include <cuda_runtime.h>
#include <cuda_bf16.h>

// Problem: B=32, N=50000, K=32, E=6, F=3
//   f[b,n,f] = leaky_relu(x[b,n]*s[f] + g[n,f]),  s[f]=sum_e W[f,e], g[n,f]=W[f,:].emb[n,:]+bias[f]
//   out[n,k] = mask * mean_b exp(-||f[b,n,:]-f[b,nbr[n,k],:]||^2)          (2*theta = 1)
//
// Identities:
//   lrelu(u) = 0.6u + 0.4|u|; positively homogeneous => pre-scale s,g by
//   sqrt(log2 e) so sum(d^2) is log2-scaled and exp(-d) = ex2(-sum d^2).
// Frozen lessons: XPAD=36 immediate-offset LDS layout; scalar FFMA-imm math;
//   128-thr CTAs; 8-lanes-per-row vectorized staging.
// This round (L1=77% wall): cp.async staging (no LDG->reg->STS round trip) and
//   fs folded into xs rows' spare cols 32..34 (smem 20->18KB => 12 CTAs/SM).

#define NMAX 50000
#define BDIM 32
#define KDIM 32
#define XPAD 36                       // 36w stride: LDS.128 conflict-free + 4 spare floats
#define C_SCALE 1.2011224087864498f   // sqrt(log2(e))
#define PWARPS 4                      // warps per pair_kernel CTA

__device__ __align__(16) float  g_xT[NMAX * BDIM];   // 6.4 MB, transposed x
__device__ float4 g_g4[NMAX];                        // 0.8 MB, pre-scaled g

// ---------------------------------------------------------------------------
// Kernel 1: transpose x (B,N) -> xT (N,B); compute scaled g4[n].
// ---------------------------------------------------------------------------
__global__ __launch_bounds__(256) void prep_kernel(
    const float* __restrict__ x,      // (B, N)
    const float* __restrict__ emb,    // (N, 6)
    const float* __restrict__ fcw,    // (3, 6)
    const float* __restrict__ fcb,    // (3,)
    int N)
{
    __shared__ float xt[32][33];
    const int n0 = blockIdx.x * 32;
    const int tx = threadIdx.x;
    const int ty = threadIdx.y;

    #pragma unroll
    for (int i = 0; i < 4; i++) {
        int b = ty + 8 * i;
        int n = n0 + tx;
        xt[b][tx] = (n < N) ? x[b * N + n] : 0.0f;
    }
    __syncthreads();

    #pragma unroll
    for (int i = 0; i < 4; i++) {
        int r = ty + 8 * i;
        int n = n0 + r;
        if (n < N) g_xT[n * BDIM + tx] = xt[tx][r];
    }

    const int tid = ty * 32 + tx;
    if (tid < 32) {
        int n = n0 + tid;
        if (n < N) {
            float e0 = emb[n * 6 + 0], e1 = emb[n * 6 + 1], e2 = emb[n * 6 + 2];
            float e3 = emb[n * 6 + 3], e4 = emb[n * 6 + 4], e5 = emb[n * 6 + 5];
            float g[3];
            #pragma unroll
            for (int f = 0; f < 3; f++) {
                g[f] = fcb[f]
                     + fcw[f * 6 + 0] * e0 + fcw[f * 6 + 1] * e1
                     + fcw[f * 6 + 2] * e2 + fcw[f * 6 + 3] * e3
                     + fcw[f * 6 + 4] * e4 + fcw[f * 6 + 5] * e5;
            }
            g_g4[n] = make_float4(C_SCALE * g[0], C_SCALE * g[1],
                                  C_SCALE * g[2], 0.0f);
        }
    }
}

// ---------------------------------------------------------------------------
// Kernel 2: one warp per node, 4 warps per CTA, 18KB smem -> 12 CTAs/SM.
//   xs row k: cols 0..31 = neighbor k's x-row; spare cols 32..35 hold self-f:
//     fs0[4g..4g+3] at row g,     offset 32..35
//     fs1[4g..4g+3] at row 8+g,   offset 32..35
//     fs2[4g..4g+3] at row 16+g,  offset 32..35
//   Staging: cp.async 16B, 8 lanes per row, 4 rows/iter, 8 iters.
//   Phase 2 (lane = k): float4 groups over b, immediate-offset LDS,
//     FFMA-imm leaky-relu distances, bare ex2.approx.
// ---------------------------------------------------------------------------
__global__ __launch_bounds__(32 * PWARPS, 12) void pair_kernel(
    const int*  __restrict__ nl,      // (N, 32)
    const float* __restrict__ fcw,    // (3, 6)
    float* __restrict__ out,          // (N, 32)
    int N)
{
    __shared__ __align__(16) float xs[PWARPS][KDIM * XPAD];   // 18432 B

    const int wid  = threadIdx.x >> 5;
    const int lane = threadIdx.x & 31;
    const int n    = blockIdx.x * PWARPS + wid;
    if (n >= N) return;

    // scaled s[f] = C * sum_e W[f,e]
    float s0 = 0.f, s1 = 0.f, s2 = 0.f;
    #pragma unroll
    for (int e = 0; e < 6; e++) {
        s0 += fcw[e];
        s1 += fcw[6 + e];
        s2 += fcw[12 + e];
    }
    s0 *= C_SCALE; s1 *= C_SCALE; s2 *= C_SCALE;

    // --- Phase 1: lane = b : self f -> xs spare cols (banks (4q+r): clean) ---
    {
        float  xv = g_xT[n * BDIM + lane];
        float4 gs = g_g4[n];
        float u0 = fmaf(xv, s0, gs.x);
        float u1 = fmaf(xv, s1, gs.y);
        float u2 = fmaf(xv, s2, gs.z);
        const int q = lane >> 2, r = lane & 3;
        xs[wid][q * XPAD + 32 + r]        = fmaf(0.4f, fabsf(u0), 0.6f * u0);
        xs[wid][(8 + q) * XPAD + 32 + r]  = fmaf(0.4f, fabsf(u1), 0.6f * u1);
        xs[wid][(16 + q) * XPAD + 32 + r] = fmaf(0.4f, fabsf(u2), 0.6f * u2);
    }

    const int   j    = nl[n * KDIM + lane];
    const int   jc   = (j < 0) ? 0 : j;
    const float mask = (j < 0) ? 0.0f : 1.0f;
    const float4 gj  = g_g4[jc];

    // Staging via cp.async: 8 lanes per row (8 float4s = full 128B row),
    // 4 rows per iteration, 8 iterations.
    {
        const float4* xT4 = (const float4*)g_xT;      // node row = 8 float4s
        const int c = lane & 7;                       // float4 index in row
        const int r = lane >> 3;                      // row-within-group 0..3
        #pragma unroll
        for (int i = 0; i < 8; i++) {
            int k  = 4 * i + r;                       // destination row
            int jj = __shfl_sync(0xffffffffu, jc, k); // that row's neighbor
            unsigned saddr = (unsigned)__cvta_generic_to_shared(
                &xs[wid][k * XPAD + 4 * c]);
            const float4* gaddr = xT4 + jj * 8 + c;
            asm volatile("cp.async.ca.shared.global [%0], [%1], 16;\n"
                         :: "r"(saddr), "l"(gaddr) : "memory");
        }
        asm volatile("cp.async.commit_group;\n" ::: "memory");
        asm volatile("cp.async.wait_group 0;\n" ::: "memory");
    }
    __syncwarp();

    // --- Phase 2: lane = k ---
    const float* xrow = &xs[wid][lane * XPAD];
    float acc0 = 0.0f, acc1 = 0.0f;

    #pragma unroll
    for (int g = 0; g < 8; g++) {
        float4 xv4  = *(const float4*)(xrow + g * 4);
        float4 f0v  = *(const float4*)&xs[wid][g * XPAD + 32];
        float4 f1v  = *(const float4*)&xs[wid][(8 + g) * XPAD + 32];
        float4 f2v  = *(const float4*)&xs[wid][(16 + g) * XPAD + 32];

        #define PAIR_STEP(XV, F0, F1, F2, ACC)                                \
        {                                                                     \
            float u0 = fmaf((XV), s0, gj.x);                                  \
            float u1 = fmaf((XV), s1, gj.y);                                  \
            float u2 = fmaf((XV), s2, gj.z);                                  \
            float d0 = fmaf(u0, -0.6f, (F0)); d0 = fmaf(fabsf(u0), -0.4f, d0);\
            float d1 = fmaf(u1, -0.6f, (F1)); d1 = fmaf(fabsf(u1), -0.4f, d1);\
            float d2 = fmaf(u2, -0.6f, (F2)); d2 = fmaf(fabsf(u2), -0.4f, d2);\
            float dn = -d0 * d0;                                              \
            dn = fmaf(d1, -d1, dn);                                           \
            dn = fmaf(d2, -d2, dn);                                           \
            float ex;                                                         \
            asm("ex2.approx.ftz.f32 %0, %1;" : "=f"(ex) : "f"(dn));           \
            (ACC) += ex;                                                      \
        }

        PAIR_STEP(xv4.x, f0v.x, f1v.x, f2v.x, acc0)
        PAIR_STEP(xv4.y, f0v.y, f1v.y, f2v.y, acc1)
        PAIR_STEP(xv4.z, f0v.z, f1v.z, f2v.z, acc0)
        PAIR_STEP(xv4.w, f0v.w, f1v.w, f2v.w, acc1)
        #undef PAIR_STEP
    }

    out[n * KDIM + lane] = (acc0 + acc1) * (1.0f / 32.0f) * mask;
}

// ---------------------------------------------------------------------------
extern "C" void kernel_launch(void* const* d_in, const int* in_sizes, int n_in,
                              void* d_out, int out_size)
{
    const float* x    = (const float*)d_in[0];   // (B, N)
    const float* emb  = (const float*)d_in[1];   // (N, 6)
    const float* fcw  = (const float*)d_in[2];   // (3, 6)
    const float* fcb  = (const float*)d_in[3];   // (3,)
    const int*   nl   = (const int*)d_in[4];     // (N, 32)
    float*       out  = (float*)d_out;           // (N, 32)

    const int N = in_sizes[1] / 6;               // 50000

    dim3 b1(32, 8);
    prep_kernel<<<(N + 31) / 32, b1>>>(x, emb, fcw, fcb, N);

    pair_kernel<<<(N + PWARPS - 1) / PWARPS, 32 * PWARPS>>>(nl, fcw, out, N);
}

// round 16
// speedup vs baseline: 1.1070x; 1.1070x over previous
#include <cuda_runtime.h>
#include <cuda_bf16.h>

// Problem: B=32, N=50000, K=32, E=6, F=3
//   f[b,n,f] = leaky_relu(x[b,n]*s[f] + g[n,f]),  s[f]=sum_e W[f,e], g[n,f]=W[f,:].emb[n,:]+bias[f]
//   out[n,k] = mask * mean_b exp(-||f[b,n,:]-f[b,nbr[n,k],:]||^2)          (2*theta = 1)
//
// Identities:
//   lrelu(u) = 0.6u + 0.4|u|; positively homogeneous => pre-scale s,g by
//   sqrt(log2 e) so sum(d^2) is log2-scaled and exp(-d) = ex2(-sum d^2).
// Frozen: XPAD=36 immediate-offset LDS; scalar FFMA-imm math; 128-thr CTAs;
//   cp.async 8-lanes-per-row staging; fs folded into xs spare cols.
// This round (issue-bound, 680 instr/warp): s precomputed in prep (kills 18
//   LDG + 18 math per warp); staging issued FIRST so phase-1/gj overlap the
//   32-line gather latency.

#define NMAX 50000
#define BDIM 32
#define KDIM 32
#define XPAD 36                       // 36w stride: LDS.128 conflict-free + 4 spare floats
#define C_SCALE 1.2011224087864498f   // sqrt(log2(e))
#define PWARPS 4                      // warps per pair_kernel CTA

__device__ __align__(16) float  g_xT[NMAX * BDIM];   // 6.4 MB, transposed x
__device__ float4 g_g4[NMAX];                        // 0.8 MB, pre-scaled g
__device__ float4 g_s;                               // pre-scaled s (x,y,z)

// ---------------------------------------------------------------------------
// Kernel 1: transpose x (B,N) -> xT (N,B); compute scaled g4[n]; scaled s.
// ---------------------------------------------------------------------------
__global__ __launch_bounds__(256) void prep_kernel(
    const float* __restrict__ x,      // (B, N)
    const float* __restrict__ emb,    // (N, 6)
    const float* __restrict__ fcw,    // (3, 6)
    const float* __restrict__ fcb,    // (3,)
    int N)
{
    __shared__ float xt[32][33];
    const int n0 = blockIdx.x * 32;
    const int tx = threadIdx.x;
    const int ty = threadIdx.y;

    #pragma unroll
    for (int i = 0; i < 4; i++) {
        int b = ty + 8 * i;
        int n = n0 + tx;
        xt[b][tx] = (n < N) ? x[b * N + n] : 0.0f;
    }
    __syncthreads();

    #pragma unroll
    for (int i = 0; i < 4; i++) {
        int r = ty + 8 * i;
        int n = n0 + r;
        if (n < N) g_xT[n * BDIM + tx] = xt[tx][r];
    }

    const int tid = ty * 32 + tx;
    if (tid < 32) {
        int n = n0 + tid;
        if (n < N) {
            float e0 = emb[n * 6 + 0], e1 = emb[n * 6 + 1], e2 = emb[n * 6 + 2];
            float e3 = emb[n * 6 + 3], e4 = emb[n * 6 + 4], e5 = emb[n * 6 + 5];
            float g[3];
            #pragma unroll
            for (int f = 0; f < 3; f++) {
                g[f] = fcb[f]
                     + fcw[f * 6 + 0] * e0 + fcw[f * 6 + 1] * e1
                     + fcw[f * 6 + 2] * e2 + fcw[f * 6 + 3] * e3
                     + fcw[f * 6 + 4] * e4 + fcw[f * 6 + 5] * e5;
            }
            g_g4[n] = make_float4(C_SCALE * g[0], C_SCALE * g[1],
                                  C_SCALE * g[2], 0.0f);
        }
    }

    // One thread computes the C-scaled column sums of W once.
    if (blockIdx.x == 0 && tid == 0) {
        float s0 = 0.f, s1 = 0.f, s2 = 0.f;
        #pragma unroll
        for (int e = 0; e < 6; e++) {
            s0 += fcw[e];
            s1 += fcw[6 + e];
            s2 += fcw[12 + e];
        }
        g_s = make_float4(C_SCALE * s0, C_SCALE * s1, C_SCALE * s2, 0.0f);
    }
}

// ---------------------------------------------------------------------------
// Kernel 2: one warp per node, 4 warps per CTA, 18KB smem -> 12 CTAs/SM.
//   Order: nl load + cp.async staging issued first; self-f / gj / s loaded
//   while the 32-line gather is in flight; then wait + compute.
//   xs row k: cols 0..31 = neighbor k's x-row; spare cols 32..35 = self-f.
// ---------------------------------------------------------------------------
__global__ __launch_bounds__(32 * PWARPS, 12) void pair_kernel(
    const int*  __restrict__ nl,      // (N, 32)
    float* __restrict__ out,          // (N, 32)
    int N)
{
    __shared__ __align__(16) float xs[PWARPS][KDIM * XPAD];   // 18432 B

    const int wid  = threadIdx.x >> 5;
    const int lane = threadIdx.x & 31;
    const int n    = blockIdx.x * PWARPS + wid;
    if (n >= N) return;

    // --- 1. Neighbor index + staging, issued before anything else ---
    const int   j    = nl[n * KDIM + lane];
    const int   jc   = (j < 0) ? 0 : j;
    const float mask = (j < 0) ? 0.0f : 1.0f;

    {
        const float4* xT4 = (const float4*)g_xT;      // node row = 8 float4s
        const int c = lane & 7;                       // float4 index in row
        const int r = lane >> 3;                      // row-within-group 0..3
        #pragma unroll
        for (int i = 0; i < 8; i++) {
            int k  = 4 * i + r;                       // destination row
            int jj = __shfl_sync(0xffffffffu, jc, k); // that row's neighbor
            unsigned saddr = (unsigned)__cvta_generic_to_shared(
                &xs[wid][k * XPAD + 4 * c]);
            const float4* gaddr = xT4 + jj * 8 + c;
            asm volatile("cp.async.ca.shared.global [%0], [%1], 16;\n"
                         :: "r"(saddr), "l"(gaddr) : "memory");
        }
        asm volatile("cp.async.commit_group;\n" ::: "memory");
    }

    // --- 2. Independent work while staging is in flight ---
    const float4 sv = g_s;
    const float  s0 = sv.x, s1 = sv.y, s2 = sv.z;
    const float4 gj = g_g4[jc];                      // neighbor g (random gather)

    {   // self f for b = lane -> xs spare cols (banks (4q+r): clean)
        float  xv = g_xT[n * BDIM + lane];
        float4 gs = g_g4[n];
        float u0 = fmaf(xv, s0, gs.x);
        float u1 = fmaf(xv, s1, gs.y);
        float u2 = fmaf(xv, s2, gs.z);
        const int q = lane >> 2, r = lane & 3;
        xs[wid][q * XPAD + 32 + r]        = fmaf(0.4f, fabsf(u0), 0.6f * u0);
        xs[wid][(8 + q) * XPAD + 32 + r]  = fmaf(0.4f, fabsf(u1), 0.6f * u1);
        xs[wid][(16 + q) * XPAD + 32 + r] = fmaf(0.4f, fabsf(u2), 0.6f * u2);
    }

    asm volatile("cp.async.wait_group 0;\n" ::: "memory");
    __syncwarp();

    // --- 3. Phase 2: lane = k ---
    const float* xrow = &xs[wid][lane * XPAD];
    float acc0 = 0.0f, acc1 = 0.0f;

    #pragma unroll
    for (int g = 0; g < 8; g++) {
        float4 xv4  = *(const float4*)(xrow + g * 4);
        float4 f0v  = *(const float4*)&xs[wid][g * XPAD + 32];
        float4 f1v  = *(const float4*)&xs[wid][(8 + g) * XPAD + 32];
        float4 f2v  = *(const float4*)&xs[wid][(16 + g) * XPAD + 32];

        #define PAIR_STEP(XV, F0, F1, F2, ACC)                                \
        {                                                                     \
            float u0 = fmaf((XV), s0, gj.x);                                  \
            float u1 = fmaf((XV), s1, gj.y);                                  \
            float u2 = fmaf((XV), s2, gj.z);                                  \
            float d0 = fmaf(u0, -0.6f, (F0)); d0 = fmaf(fabsf(u0), -0.4f, d0);\
            float d1 = fmaf(u1, -0.6f, (F1)); d1 = fmaf(fabsf(u1), -0.4f, d1);\
            float d2 = fmaf(u2, -0.6f, (F2)); d2 = fmaf(fabsf(u2), -0.4f, d2);\
            float dn = -d0 * d0;                                              \
            dn = fmaf(d1, -d1, dn);                                           \
            dn = fmaf(d2, -d2, dn);                                           \
            float ex;                                                         \
            asm("ex2.approx.ftz.f32 %0, %1;" : "=f"(ex) : "f"(dn));           \
            (ACC) += ex;                                                      \
        }

        PAIR_STEP(xv4.x, f0v.x, f1v.x, f2v.x, acc0)
        PAIR_STEP(xv4.y, f0v.y, f1v.y, f2v.y, acc1)
        PAIR_STEP(xv4.z, f0v.z, f1v.z, f2v.z, acc0)
        PAIR_STEP(xv4.w, f0v.w, f1v.w, f2v.w, acc1)
        #undef PAIR_STEP
    }

    out[n * KDIM + lane] = (acc0 + acc1) * (1.0f / 32.0f) * mask;
}

// ---------------------------------------------------------------------------
extern "C" void kernel_launch(void* const* d_in, const int* in_sizes, int n_in,
                              void* d_out, int out_size)
{
    const float* x    = (const float*)d_in[0];   // (B, N)
    const float* emb  = (const float*)d_in[1];   // (N, 6)
    const float* fcw  = (const float*)d_in[2];   // (3, 6)
    const float* fcb  = (const float*)d_in[3];   // (3,)
    const int*   nl   = (const int*)d_in[4];     // (N, 32)
    float*       out  = (float*)d_out;           // (N, 32)

    const int N = in_sizes[1] / 6;               // 50000

    dim3 b1(32, 8);
    prep_kernel<<<(N + 31) / 32, b1>>>(x, emb, fcw, fcb, N);

    pair_kernel<<<(N + PWARPS - 1) / PWARPS, 32 * PWARPS>>>(nl, out, N);
}